// round 10
// baseline (speedup 1.0000x reference)
#include <cuda_runtime.h>
#include <cuda_bf16.h>
#include <cstdint>

// Problem constants (fixed by the dataset)
#define BB 16
#define TT 32641
#define EE 128
#define LL (TT + EE - 1)            // 32768 groups (power of two)
#define RR 32                       // rows per tile
#define TILES ((TT + RR - 1) / RR)  // 1021 (tile 1020 is partial: 1 valid row)
#define TPC 16                      // tiles per chunk
#define CHUNKS ((TILES + TPC - 1) / TPC) // 64 -> grid 64x16 = 1024 = ONE wave
#define TILE_BYTES (RR * EE * 4)    // 16384
#define TILE_FLOATS (RR * EE)       // 4096

// Scratch: per-(batch, group) partial sums (4 MB). Zero at module load;
// postinit (runs AFTER finalize each replay) re-zeroes for the next replay.
__device__ float g_S1[BB * LL];
__device__ float g_S2[BB * LL];

// ---------------------------------------------------------------------------
// PTX helpers
// ---------------------------------------------------------------------------
__device__ __forceinline__ uint32_t smem_u32(const void* p) {
    uint32_t a;
    asm("{ .reg .u64 t; cvta.to.shared.u64 t, %1; cvt.u32.u64 %0, t; }"
        : "=r"(a) : "l"(p));
    return a;
}
__device__ __forceinline__ void mbar_init(uint32_t m, uint32_t cnt) {
    asm volatile("mbarrier.init.shared.b64 [%0], %1;" :: "r"(m), "r"(cnt) : "memory");
}
__device__ __forceinline__ void mbar_expect_tx(uint32_t m, uint32_t bytes) {
    asm volatile("mbarrier.arrive.expect_tx.shared.b64 _, [%0], %1;"
                 :: "r"(m), "r"(bytes) : "memory");
}
__device__ __forceinline__ void mbar_wait(uint32_t m, uint32_t phase) {
    asm volatile(
        "{\n\t.reg .pred P;\n\t"
        "WL_%=:\n\t"
        "mbarrier.try_wait.parity.acquire.cta.shared::cta.b64 P, [%0], %1, 0x989680;\n\t"
        "@P bra.uni WD_%=;\n\t"
        "bra.uni WL_%=;\n\t"
        "WD_%=:\n\t}"
        :: "r"(m), "r"(phase) : "memory");
}
// 1-D bulk async copy global -> shared (TMA path; no per-lane L1 wavefronts)
__device__ __forceinline__ void bulk_ld(uint32_t dst, const void* src,
                                        uint32_t bytes, uint32_t m) {
    asm volatile(
        "cp.async.bulk.shared::cta.global.mbarrier::complete_tx::bytes "
        "[%0], [%1], %2, [%3];"
        :: "r"(dst), "l"(src), "r"(bytes), "r"(m) : "memory");
}

// ---------------------------------------------------------------------------
// Diagonal walk over one 32x128 tile in smem; nrows = valid rows (rest of
// tile may hold stale/garbage data and must not be read).
// Thread d owns group t = r0 + d. Lanes consecutive at fixed i -> no
// bank conflicts. Fire-and-forget atomics.
// ---------------------------------------------------------------------------
__device__ __forceinline__ void walk_tile(const float* cur, int r0, int b, int nrows) {
    const int d = threadIdx.x;
    if (d < nrows + EE - 1) {
        const int i_lo = max(0, d - (EE - 1));
        const int i_hi = min(nrows - 1, d);
        float s1 = 0.0f, s2 = 0.0f;
        #pragma unroll 4
        for (int i = i_lo; i <= i_hi; ++i) {
            float v = cur[i * EE + (d - i)];
            s1 += v;
            s2 = fmaf(v, v, s2);
        }
        const int t = r0 + d;
        atomicAdd(&g_S1[b * LL + t], s1);
        atomicAdd(&g_S2[b * LL + t], s2);
    }
}

// ---------------------------------------------------------------------------
// Kernel 1 (FIRST in stream -> profiled): TMA-fed anti-diagonal partials.
// Single wave: 1024 blocks, each streams up to 16 tiles through a depth-2
// cp.async.bulk double buffer. Partial last tile handled via nrows and a
// clipped bulk-copy size (TMA transfers only the valid bytes).
// ---------------------------------------------------------------------------
__global__ void __launch_bounds__(256) tcl_diag_kernel(const float* __restrict__ x,
                                                       float* __restrict__ out) {
    extern __shared__ float buf[];                 // 2 * TILE_FLOATS
    __shared__ __align__(8) unsigned long long mbar_store[2];

    const int c   = blockIdx.x;
    const int b   = blockIdx.y;
    const int tid = threadIdx.x;
    const float* xb = x + (size_t)b * TT * EE;

    if (c == 0 && b == 0 && tid == 0) out[0] = 0.0f;

    const int k0 = c * TPC;
    const int nk = min(k0 + TPC, TILES) - k0;      // 16, or 13 for last chunk
    if (nk <= 0) return;

    // bytes of valid data in tile (k0+kk): full except global tile 1020
    auto tile_rows = [&](int kk) -> int {
        return min(TT - (k0 + kk) * RR, RR);       // 32, or 1 for tile 1020
    };

    const uint32_t sbuf = smem_u32(buf);
    const uint32_t m0 = smem_u32(&mbar_store[0]);
    const uint32_t m1 = smem_u32(&mbar_store[1]);

    if (tid == 0) { mbar_init(m0, 1); mbar_init(m1, 1); }
    __syncthreads();

    if (tid == 0) {
        uint32_t bytes0 = (uint32_t)tile_rows(0) * EE * 4;
        mbar_expect_tx(m0, bytes0);
        bulk_ld(sbuf, xb + (size_t)(k0 + 0) * TILE_FLOATS, bytes0, m0);
        if (nk > 1) {
            uint32_t bytes1 = (uint32_t)tile_rows(1) * EE * 4;
            mbar_expect_tx(m1, bytes1);
            bulk_ld(sbuf + TILE_BYTES, xb + (size_t)(k0 + 1) * TILE_FLOATS, bytes1, m1);
        }
    }

    for (int kk = 0; kk < nk; ++kk) {
        const uint32_t m = (kk & 1) ? m1 : m0;
        mbar_wait(m, (kk >> 1) & 1);

        walk_tile(buf + (kk & 1) * TILE_FLOATS, (k0 + kk) * RR, b, tile_rows(kk));

        __syncthreads();   // everyone done with this buffer
        if (kk + 2 < nk && tid == 0) {
            uint32_t bytes = (uint32_t)tile_rows(kk + 2) * EE * 4;
            mbar_expect_tx(m, bytes);
            bulk_ld(sbuf + (kk & 1) * TILE_BYTES,
                    xb + (size_t)(k0 + kk + 2) * TILE_FLOATS, bytes, m);
        }
    }
}

// ---------------------------------------------------------------------------
// Kernel 2: var = S2/c - (S1/c)^2, mean over (b,t), * 0.1.
// One float4 per thread from each array (max MLP); plain atomicAdd into
// out[0] (zeroed by diag earlier in the stream).
// ---------------------------------------------------------------------------
__global__ void __launch_bounds__(256) tcl_finalize_kernel(float* __restrict__ out) {
    __shared__ float red[8];
    const int i = blockIdx.x * blockDim.x + threadIdx.x;   // < BB*LL/4
    float4 s1v = ((const float4*)g_S1)[i];
    float4 s2v = ((const float4*)g_S2)[i];

    float local = 0.0f;
    const int g0 = i * 4;
    #pragma unroll
    for (int j = 0; j < 4; ++j) {
        int t  = (g0 + j) & (LL - 1);              // LL is a power of two
        int ci = min(min(t + 1, EE), LL - t);
        float inv_c = 1.0f / (float)ci;
        float s1 = (j == 0) ? s1v.x : (j == 1) ? s1v.y : (j == 2) ? s1v.z : s1v.w;
        float s2 = (j == 0) ? s2v.x : (j == 1) ? s2v.y : (j == 2) ? s2v.z : s2v.w;
        float mean = s1 * inv_c;
        local += s2 * inv_c - mean * mean;
    }

    #pragma unroll
    for (int o = 16; o; o >>= 1) local += __shfl_down_sync(0xFFFFFFFFu, local, o);
    if ((threadIdx.x & 31) == 0) red[threadIdx.x >> 5] = local;
    __syncthreads();
    if (threadIdx.x < 8) {
        float v = red[threadIdx.x];
        #pragma unroll
        for (int o = 4; o; o >>= 1) v += __shfl_down_sync(0xFFu, v, o);
        if (threadIdx.x == 0) {
            atomicAdd(out, v * (0.1f / ((float)BB * (float)LL)));
        }
    }
}

// ---------------------------------------------------------------------------
// Kernel 3: zero scratch for the NEXT replay (runs after finalize).
// ---------------------------------------------------------------------------
__global__ void __launch_bounds__(256) tcl_postinit_kernel() {
    const int i = blockIdx.x * blockDim.x + threadIdx.x;   // < BB*LL/4
    float4 z = make_float4(0.f, 0.f, 0.f, 0.f);
    ((float4*)g_S1)[i] = z;
    ((float4*)g_S2)[i] = z;
}

// ---------------------------------------------------------------------------
extern "C" void kernel_launch(void* const* d_in, const int* in_sizes, int n_in,
                              void* d_out, int out_size) {
    const float* x = (const float*)d_in[0];
    float* out = (float*)d_out;

    const int diag_smem = 2 * TILE_BYTES;                  // 32 KB
    cudaFuncSetAttribute(tcl_diag_kernel,
                         cudaFuncAttributeMaxDynamicSharedMemorySize, diag_smem);
    dim3 grid(CHUNKS, BB);                                 // 64 x 16 = 1024
    tcl_diag_kernel<<<grid, 256, diag_smem>>>(x, out);

    tcl_finalize_kernel<<<BB * LL / 4 / 256, 256>>>(out);  // 512 blocks

    tcl_postinit_kernel<<<BB * LL / 4 / 256, 256>>>();     // 512 blocks
}

// round 12
// speedup vs baseline: 1.1214x; 1.1214x over previous
#include <cuda_runtime.h>
#include <cuda_bf16.h>
#include <cstdint>

// Problem constants (fixed by the dataset)
#define BB 16
#define TT 32641
#define EE 128
#define LL (TT + EE - 1)            // 32768 groups (power of two)
#define RR 16                       // rows per tile (small -> fine-grained pipeline)
#define TILES ((TT + RR - 1) / RR)  // 2041 (tile 2040 partial: 1 valid row)
#define TPC 8                       // tiles per chunk
#define CHUNKS ((TILES + TPC - 1) / TPC) // 256 -> grid 256x16 = 4096 (4 waves)
#define NBUF 4                      // ring depth
#define TILE_BYTES (RR * EE * 4)    // 8192
#define TILE_FLOATS (RR * EE)       // 2048

// Scratch: per-(batch, group) partial sums (4 MB). Zero at module load;
// postinit (runs AFTER finalize each replay) re-zeroes for the next replay.
__device__ float g_S1[BB * LL];
__device__ float g_S2[BB * LL];

// ---------------------------------------------------------------------------
// PTX helpers
// ---------------------------------------------------------------------------
__device__ __forceinline__ uint32_t smem_u32(const void* p) {
    uint32_t a;
    asm("{ .reg .u64 t; cvta.to.shared.u64 t, %1; cvt.u32.u64 %0, t; }"
        : "=r"(a) : "l"(p));
    return a;
}
__device__ __forceinline__ void mbar_init(uint32_t m, uint32_t cnt) {
    asm volatile("mbarrier.init.shared.b64 [%0], %1;" :: "r"(m), "r"(cnt) : "memory");
}
__device__ __forceinline__ void mbar_expect_tx(uint32_t m, uint32_t bytes) {
    asm volatile("mbarrier.arrive.expect_tx.shared.b64 _, [%0], %1;"
                 :: "r"(m), "r"(bytes) : "memory");
}
__device__ __forceinline__ void mbar_wait(uint32_t m, uint32_t phase) {
    asm volatile(
        "{\n\t.reg .pred P;\n\t"
        "WL_%=:\n\t"
        "mbarrier.try_wait.parity.acquire.cta.shared::cta.b64 P, [%0], %1, 0x989680;\n\t"
        "@P bra.uni WD_%=;\n\t"
        "bra.uni WL_%=;\n\t"
        "WD_%=:\n\t}"
        :: "r"(m), "r"(phase) : "memory");
}
// 1-D bulk async copy global -> shared (TMA path; no per-lane L1 wavefronts)
__device__ __forceinline__ void bulk_ld(uint32_t dst, const void* src,
                                        uint32_t bytes, uint32_t m) {
    asm volatile(
        "cp.async.bulk.shared::cta.global.mbarrier::complete_tx::bytes "
        "[%0], [%1], %2, [%3];"
        :: "r"(dst), "l"(src), "r"(bytes), "r"(m) : "memory");
}

// ---------------------------------------------------------------------------
// Diagonal walk over one RRx128 tile in smem; nrows = valid rows.
// Thread d owns group t = r0 + d. Lanes consecutive at fixed i -> no bank
// conflicts. Fire-and-forget atomics.
// ---------------------------------------------------------------------------
__device__ __forceinline__ void walk_tile(const float* cur, int r0, int b, int nrows) {
    const int d = threadIdx.x;
    if (d < nrows + EE - 1) {                      // up to 143 diagonals
        const int i_lo = max(0, d - (EE - 1));
        const int i_hi = min(nrows - 1, d);
        float s1 = 0.0f, s2 = 0.0f;
        #pragma unroll 4
        for (int i = i_lo; i <= i_hi; ++i) {
            float v = cur[i * EE + (d - i)];
            s1 += v;
            s2 = fmaf(v, v, s2);
        }
        const int t = r0 + d;
        atomicAdd(&g_S1[b * LL + t], s1);
        atomicAdd(&g_S2[b * LL + t], s2);
    }
}

// ---------------------------------------------------------------------------
// Kernel 1 (FIRST in stream -> profiled): TMA-fed anti-diagonal partials.
// 4096 blocks (4 waves of oversubscription), each streams up to 8 tiles of
// 8 KB through a depth-4 cp.async.bulk ring: wait quantum halved, 3 spare
// transfers in flight absorb latency jitter.
// ---------------------------------------------------------------------------
__global__ void __launch_bounds__(256) tcl_diag_kernel(const float* __restrict__ x,
                                                       float* __restrict__ out) {
    extern __shared__ float buf[];                 // NBUF * TILE_FLOATS
    __shared__ __align__(8) unsigned long long mbar_store[NBUF];

    const int c   = blockIdx.x;
    const int b   = blockIdx.y;
    const int tid = threadIdx.x;
    const float* xb = x + (size_t)b * TT * EE;

    if (c == 0 && b == 0 && tid == 0) out[0] = 0.0f;

    const int k0 = c * TPC;
    const int nk = min(k0 + TPC, TILES) - k0;      // 8, or 1 for last chunk
    if (nk <= 0) return;

    auto tile_rows = [&](int kk) -> int {
        return min(TT - (k0 + kk) * RR, RR);       // 16, or 1 for tile 2040
    };

    const uint32_t sbuf = smem_u32(buf);
    uint32_t mb[NBUF];
    #pragma unroll
    for (int j = 0; j < NBUF; ++j) mb[j] = smem_u32(&mbar_store[j]);

    if (tid == 0) {
        #pragma unroll
        for (int j = 0; j < NBUF; ++j) mbar_init(mb[j], 1);
    }
    __syncthreads();

    // Prefetch up to NBUF tiles.
    if (tid == 0) {
        #pragma unroll
        for (int j = 0; j < NBUF; ++j) {
            if (j < nk) {
                uint32_t bytes = (uint32_t)tile_rows(j) * EE * 4;
                mbar_expect_tx(mb[j], bytes);
                bulk_ld(sbuf + j * TILE_BYTES,
                        xb + (size_t)(k0 + j) * TILE_FLOATS, bytes, mb[j]);
            }
        }
    }

    for (int kk = 0; kk < nk; ++kk) {
        const int j = kk & (NBUF - 1);
        mbar_wait(mb[j], (kk >> 2) & 1);

        walk_tile(buf + j * TILE_FLOATS, (k0 + kk) * RR, b, tile_rows(kk));

        __syncthreads();   // everyone done with this buffer
        if (kk + NBUF < nk && tid == 0) {
            uint32_t bytes = (uint32_t)tile_rows(kk + NBUF) * EE * 4;
            mbar_expect_tx(mb[j], bytes);
            bulk_ld(sbuf + j * TILE_BYTES,
                    xb + (size_t)(k0 + kk + NBUF) * TILE_FLOATS, bytes, mb[j]);
        }
    }
}

// ---------------------------------------------------------------------------
// Kernel 2: var = S2/c - (S1/c)^2, mean over (b,t), * 0.1.
// One float4 per thread from each array (max MLP); plain atomicAdd into
// out[0] (zeroed by diag earlier in the stream).
// ---------------------------------------------------------------------------
__global__ void __launch_bounds__(256) tcl_finalize_kernel(float* __restrict__ out) {
    __shared__ float red[8];
    const int i = blockIdx.x * blockDim.x + threadIdx.x;   // < BB*LL/4
    float4 s1v = ((const float4*)g_S1)[i];
    float4 s2v = ((const float4*)g_S2)[i];

    float local = 0.0f;
    const int g0 = i * 4;
    #pragma unroll
    for (int j = 0; j < 4; ++j) {
        int t  = (g0 + j) & (LL - 1);              // LL is a power of two
        int ci = min(min(t + 1, EE), LL - t);
        float inv_c = 1.0f / (float)ci;
        float s1 = (j == 0) ? s1v.x : (j == 1) ? s1v.y : (j == 2) ? s1v.z : s1v.w;
        float s2 = (j == 0) ? s2v.x : (j == 1) ? s2v.y : (j == 2) ? s2v.z : s2v.w;
        float mean = s1 * inv_c;
        local += s2 * inv_c - mean * mean;
    }

    #pragma unroll
    for (int o = 16; o; o >>= 1) local += __shfl_down_sync(0xFFFFFFFFu, local, o);
    if ((threadIdx.x & 31) == 0) red[threadIdx.x >> 5] = local;
    __syncthreads();
    if (threadIdx.x < 8) {
        float v = red[threadIdx.x];
        #pragma unroll
        for (int o = 4; o; o >>= 1) v += __shfl_down_sync(0xFFu, v, o);
        if (threadIdx.x == 0) {
            atomicAdd(out, v * (0.1f / ((float)BB * (float)LL)));
        }
    }
}

// ---------------------------------------------------------------------------
// Kernel 3: zero scratch for the NEXT replay (runs after finalize).
// ---------------------------------------------------------------------------
__global__ void __launch_bounds__(256) tcl_postinit_kernel() {
    const int i = blockIdx.x * blockDim.x + threadIdx.x;   // < BB*LL/4
    float4 z = make_float4(0.f, 0.f, 0.f, 0.f);
    ((float4*)g_S1)[i] = z;
    ((float4*)g_S2)[i] = z;
}

// ---------------------------------------------------------------------------
extern "C" void kernel_launch(void* const* d_in, const int* in_sizes, int n_in,
                              void* d_out, int out_size) {
    const float* x = (const float*)d_in[0];
    float* out = (float*)d_out;

    const int diag_smem = NBUF * TILE_BYTES;               // 32 KB
    cudaFuncSetAttribute(tcl_diag_kernel,
                         cudaFuncAttributeMaxDynamicSharedMemorySize, diag_smem);
    dim3 grid(CHUNKS, BB);                                 // 256 x 16 = 4096
    tcl_diag_kernel<<<grid, 256, diag_smem>>>(x, out);

    tcl_finalize_kernel<<<BB * LL / 4 / 256, 256>>>(out);  // 512 blocks

    tcl_postinit_kernel<<<BB * LL / 4 / 256, 256>>>();     // 512 blocks
}

// round 15
// speedup vs baseline: 1.1842x; 1.0561x over previous
#include <cuda_runtime.h>
#include <cuda_bf16.h>
#include <cstdint>

// Problem constants (fixed by the dataset)
#define BB 16
#define TT 32641
#define EE 128
#define LL (TT + EE - 1)            // 32768 groups (power of two)
#define RR 32                       // rows per tile
#define TILES ((TT + RR - 1) / RR)  // 1021 (tile 1020 partial: 1 valid row)
#define TPC 4                       // tiles per chunk -> 128 rows
#define CHUNKS ((TILES + TPC - 1) / TPC) // 256 -> grid 256x16 = 4096
#define NDIAG 255                   // diagonals per chunk (TPC*RR + EE - 1 = 255)
#define TILE_BYTES (RR * EE * 4)    // 16384
#define TILE_FLOATS (RR * EE)       // 4096

// Scratch: per-(batch, group) partial sums (4 MB). Zero at module load;
// finalize re-zeroes after reading (fire-and-forget), so replays start clean.
__device__ float g_S1[BB * LL];
__device__ float g_S2[BB * LL];

// ---------------------------------------------------------------------------
// PTX helpers
// ---------------------------------------------------------------------------
__device__ __forceinline__ uint32_t smem_u32(const void* p) {
    uint32_t a;
    asm("{ .reg .u64 t; cvta.to.shared.u64 t, %1; cvt.u32.u64 %0, t; }"
        : "=r"(a) : "l"(p));
    return a;
}
__device__ __forceinline__ void mbar_init(uint32_t m, uint32_t cnt) {
    asm volatile("mbarrier.init.shared.b64 [%0], %1;" :: "r"(m), "r"(cnt) : "memory");
}
__device__ __forceinline__ void mbar_expect_tx(uint32_t m, uint32_t bytes) {
    asm volatile("mbarrier.arrive.expect_tx.shared.b64 _, [%0], %1;"
                 :: "r"(m), "r"(bytes) : "memory");
}
__device__ __forceinline__ void mbar_wait(uint32_t m, uint32_t phase) {
    asm volatile(
        "{\n\t.reg .pred P;\n\t"
        "WL_%=:\n\t"
        "mbarrier.try_wait.parity.acquire.cta.shared::cta.b64 P, [%0], %1, 0x989680;\n\t"
        "@P bra.uni WD_%=;\n\t"
        "bra.uni WL_%=;\n\t"
        "WD_%=:\n\t}"
        :: "r"(m), "r"(phase) : "memory");
}
// 1-D bulk async copy global -> shared (TMA path; no per-lane L1 wavefronts)
__device__ __forceinline__ void bulk_ld(uint32_t dst, const void* src,
                                        uint32_t bytes, uint32_t m) {
    asm volatile(
        "cp.async.bulk.shared::cta.global.mbarrier::complete_tx::bytes "
        "[%0], [%1], %2, [%3];"
        :: "r"(dst), "l"(src), "r"(bytes), "r"(m) : "memory");
}

// ---------------------------------------------------------------------------
// Kernel 1 (FIRST in stream -> profiled): TMA-fed anti-diagonal partials.
// Fixed-diagonal ownership: thread d owns group t = K + d for the WHOLE
// chunk (K = chunk base row). Per tile it reads its row overlap and
// accumulates s1/s2 in registers; ONE atomic pair per thread per chunk
// (2.5x fewer atomics than per-tile emission). Depth-2 TMA double buffer.
// ---------------------------------------------------------------------------
__global__ void __launch_bounds__(256) tcl_diag_kernel(const float* __restrict__ x,
                                                       float* __restrict__ out) {
    extern __shared__ float buf[];                 // 2 * TILE_FLOATS
    __shared__ __align__(8) unsigned long long mbar_store[2];

    const int c   = blockIdx.x;
    const int b   = blockIdx.y;
    const int tid = threadIdx.x;
    const float* xb = x + (size_t)b * TT * EE;

    if (c == 0 && b == 0 && tid == 0) out[0] = 0.0f;

    const int k0 = c * TPC;
    const int nk = min(k0 + TPC, TILES) - k0;      // 4, or 1 for last chunk
    if (nk <= 0) return;
    const int K = k0 * RR;                         // chunk base row / base diagonal

    auto tile_rows = [&](int kk) -> int {
        return min(TT - (k0 + kk) * RR, RR);       // 32, or 1 for tile 1020
    };

    const uint32_t sbuf = smem_u32(buf);
    const uint32_t m0 = smem_u32(&mbar_store[0]);
    const uint32_t m1 = smem_u32(&mbar_store[1]);

    if (tid == 0) { mbar_init(m0, 1); mbar_init(m1, 1); }
    __syncthreads();

    if (tid == 0) {
        uint32_t bytes0 = (uint32_t)tile_rows(0) * EE * 4;
        mbar_expect_tx(m0, bytes0);
        bulk_ld(sbuf, xb + (size_t)(k0 + 0) * TILE_FLOATS, bytes0, m0);
        if (nk > 1) {
            uint32_t bytes1 = (uint32_t)tile_rows(1) * EE * 4;
            mbar_expect_tx(m1, bytes1);
            bulk_ld(sbuf + TILE_BYTES, xb + (size_t)(k0 + 1) * TILE_FLOATS, bytes1, m1);
        }
    }

    float s1 = 0.0f, s2 = 0.0f;                    // accumulators for t = K + tid

    for (int kk = 0; kk < nk; ++kk) {
        const uint32_t m = (kk & 1) ? m1 : m0;
        mbar_wait(m, (kk >> 1) & 1);
        const float* cur = buf + (kk & 1) * TILE_FLOATS;

        // Rows (chunk-relative) this thread's diagonal touches in this tile:
        // i in [max(d-127, kk*RR), min(d, kk*RR + nrows-1)], read col d-i.
        const int nrows = tile_rows(kk);
        const int rbase = kk * RR;
        const int i_lo  = max(tid - (EE - 1), rbase);
        const int i_hi  = min(tid, rbase + nrows - 1);
        #pragma unroll 4
        for (int i = i_lo; i <= i_hi; ++i) {
            float v = cur[(i - rbase) * EE + (tid - i)];  // lanes consecutive: no conflicts
            s1 += v;
            s2 = fmaf(v, v, s2);
        }

        __syncthreads();   // everyone done with this buffer
        if (kk + 2 < nk && tid == 0) {
            uint32_t bytes = (uint32_t)tile_rows(kk + 2) * EE * 4;
            mbar_expect_tx(m, bytes);
            bulk_ld(sbuf + (kk & 1) * TILE_BYTES,
                    xb + (size_t)(k0 + kk + 2) * TILE_FLOATS, bytes, m);
        }
    }

    // Single atomic pair per thread per chunk.
    const int t    = K + tid;
    const int tmax = min(K + nk * RR, TT) - 1 + (EE - 1);
    if (tid < NDIAG && t <= tmax) {
        atomicAdd(&g_S1[b * LL + t], s1);
        atomicAdd(&g_S2[b * LL + t], s2);
    }
}

// ---------------------------------------------------------------------------
// Kernel 2: var = S2/c - (S1/c)^2, mean over (b,t), * 0.1; then reset the
// scratch with fire-and-forget float4 zero-stores (replaces postinit).
// One float4 per thread from each array (max MLP); plain atomicAdd into
// out[0] (zeroed by diag earlier in the stream).
// ---------------------------------------------------------------------------
__global__ void __launch_bounds__(256) tcl_finalize_kernel(float* __restrict__ out) {
    __shared__ float red[8];
    const int i = blockIdx.x * blockDim.x + threadIdx.x;   // < BB*LL/4
    float4 s1v = ((const float4*)g_S1)[i];
    float4 s2v = ((const float4*)g_S2)[i];

    // Reset for the next replay (stores drain while we reduce; no fence needed
    // for correctness of THIS run's output).
    float4 z = make_float4(0.f, 0.f, 0.f, 0.f);
    ((float4*)g_S1)[i] = z;
    ((float4*)g_S2)[i] = z;

    float local = 0.0f;
    const int g0 = i * 4;
    #pragma unroll
    for (int j = 0; j < 4; ++j) {
        int t  = (g0 + j) & (LL - 1);              // LL is a power of two
        int ci = min(min(t + 1, EE), LL - t);
        float inv_c = 1.0f / (float)ci;
        float s1 = (j == 0) ? s1v.x : (j == 1) ? s1v.y : (j == 2) ? s1v.z : s1v.w;
        float s2 = (j == 0) ? s2v.x : (j == 1) ? s2v.y : (j == 2) ? s2v.z : s2v.w;
        float mean = s1 * inv_c;
        local += s2 * inv_c - mean * mean;
    }

    #pragma unroll
    for (int o = 16; o; o >>= 1) local += __shfl_down_sync(0xFFFFFFFFu, local, o);
    if ((threadIdx.x & 31) == 0) red[threadIdx.x >> 5] = local;
    __syncthreads();
    if (threadIdx.x < 8) {
        float v = red[threadIdx.x];
        #pragma unroll
        for (int o = 4; o; o >>= 1) v += __shfl_down_sync(0xFFu, v, o);
        if (threadIdx.x == 0) {
            atomicAdd(out, v * (0.1f / ((float)BB * (float)LL)));
        }
    }
}

// ---------------------------------------------------------------------------
extern "C" void kernel_launch(void* const* d_in, const int* in_sizes, int n_in,
                              void* d_out, int out_size) {
    const float* x = (const float*)d_in[0];
    float* out = (float*)d_out;

    const int diag_smem = 2 * TILE_BYTES;                  // 32 KB
    cudaFuncSetAttribute(tcl_diag_kernel,
                         cudaFuncAttributeMaxDynamicSharedMemorySize, diag_smem);
    dim3 grid(CHUNKS, BB);                                 // 256 x 16 = 4096
    tcl_diag_kernel<<<grid, 256, diag_smem>>>(x, out);

    tcl_finalize_kernel<<<BB * LL / 4 / 256, 256>>>(out);  // 512 blocks
}

// round 16
// speedup vs baseline: 1.2384x; 1.0457x over previous
#include <cuda_runtime.h>
#include <cuda_bf16.h>
#include <cstdint>

// Problem constants (fixed by the dataset)
#define BB 16
#define TT 32641
#define EE 128
#define LL (TT + EE - 1)            // 32768 groups (power of two)
#define RR 32                       // rows per tile
#define TILES ((TT + RR - 1) / RR)  // 1021 (tile 1020 partial: 1 valid row)
#define TPC 4                       // tiles per chunk -> 128 rows
#define CHUNKS ((TILES + TPC - 1) / TPC) // 256 -> grid 256x16 = 4096
#define NDIAG 255                   // diagonals per chunk (TPC*RR + EE - 1)
#define TILE_BYTES (RR * EE * 4)    // 16384
#define TILE_FLOATS (RR * EE)       // 4096

// Scratch: per-(batch, group) partial sums (4 MB). Zero at module load;
// postinit (AFTER finalize) re-zeroes for the next replay.
__device__ float g_S1[BB * LL];
__device__ float g_S2[BB * LL];

// ---------------------------------------------------------------------------
// PTX helpers
// ---------------------------------------------------------------------------
__device__ __forceinline__ uint32_t smem_u32(const void* p) {
    uint32_t a;
    asm("{ .reg .u64 t; cvta.to.shared.u64 t, %1; cvt.u32.u64 %0, t; }"
        : "=r"(a) : "l"(p));
    return a;
}
__device__ __forceinline__ void mbar_init(uint32_t m, uint32_t cnt) {
    asm volatile("mbarrier.init.shared.b64 [%0], %1;" :: "r"(m), "r"(cnt) : "memory");
}
__device__ __forceinline__ void mbar_expect_tx(uint32_t m, uint32_t bytes) {
    asm volatile("mbarrier.arrive.expect_tx.shared.b64 _, [%0], %1;"
                 :: "r"(m), "r"(bytes) : "memory");
}
__device__ __forceinline__ void mbar_wait(uint32_t m, uint32_t phase) {
    asm volatile(
        "{\n\t.reg .pred P;\n\t"
        "WL_%=:\n\t"
        "mbarrier.try_wait.parity.acquire.cta.shared::cta.b64 P, [%0], %1, 0x989680;\n\t"
        "@P bra.uni WD_%=;\n\t"
        "bra.uni WL_%=;\n\t"
        "WD_%=:\n\t}"
        :: "r"(m), "r"(phase) : "memory");
}
// 1-D bulk async copy global -> shared (TMA path; no per-lane L1 wavefronts)
__device__ __forceinline__ void bulk_ld(uint32_t dst, const void* src,
                                        uint32_t bytes, uint32_t m) {
    asm volatile(
        "cp.async.bulk.shared::cta.global.mbarrier::complete_tx::bytes "
        "[%0], [%1], %2, [%3];"
        :: "r"(dst), "l"(src), "r"(bytes), "r"(m) : "memory");
}

// ---------------------------------------------------------------------------
// Kernel 1 (FIRST in stream -> profiled): TMA-fed anti-diagonal partials.
// Fixed-diagonal ownership: thread d owns group t = K + d for the WHOLE
// chunk; per-tile row-overlap reads accumulate s1/s2 in registers; ONE
// atomic pair per thread per chunk. Depth-2 TMA double buffer.
// ---------------------------------------------------------------------------
__global__ void __launch_bounds__(256) tcl_diag_kernel(const float* __restrict__ x,
                                                       float* __restrict__ out) {
    extern __shared__ float buf[];                 // 2 * TILE_FLOATS
    __shared__ __align__(8) unsigned long long mbar_store[2];

    const int c   = blockIdx.x;
    const int b   = blockIdx.y;
    const int tid = threadIdx.x;
    const float* xb = x + (size_t)b * TT * EE;

    if (c == 0 && b == 0 && tid == 0) out[0] = 0.0f;

    const int k0 = c * TPC;
    const int nk = min(k0 + TPC, TILES) - k0;      // 4, or 1 for last chunk
    if (nk <= 0) return;
    const int K = k0 * RR;                         // chunk base row / base diagonal

    auto tile_rows = [&](int kk) -> int {
        return min(TT - (k0 + kk) * RR, RR);       // 32, or 1 for tile 1020
    };

    const uint32_t sbuf = smem_u32(buf);
    const uint32_t m0 = smem_u32(&mbar_store[0]);
    const uint32_t m1 = smem_u32(&mbar_store[1]);

    if (tid == 0) { mbar_init(m0, 1); mbar_init(m1, 1); }
    __syncthreads();

    if (tid == 0) {
        uint32_t bytes0 = (uint32_t)tile_rows(0) * EE * 4;
        mbar_expect_tx(m0, bytes0);
        bulk_ld(sbuf, xb + (size_t)(k0 + 0) * TILE_FLOATS, bytes0, m0);
        if (nk > 1) {
            uint32_t bytes1 = (uint32_t)tile_rows(1) * EE * 4;
            mbar_expect_tx(m1, bytes1);
            bulk_ld(sbuf + TILE_BYTES, xb + (size_t)(k0 + 1) * TILE_FLOATS, bytes1, m1);
        }
    }

    float s1 = 0.0f, s2 = 0.0f;                    // accumulators for t = K + tid

    for (int kk = 0; kk < nk; ++kk) {
        const uint32_t m = (kk & 1) ? m1 : m0;
        mbar_wait(m, (kk >> 1) & 1);
        const float* cur = buf + (kk & 1) * TILE_FLOATS;

        // Rows (chunk-relative) this thread's diagonal touches in this tile:
        // i in [max(d-127, kk*RR), min(d, kk*RR + nrows-1)], read col d-i.
        const int nrows = tile_rows(kk);
        const int rbase = kk * RR;
        const int i_lo  = max(tid - (EE - 1), rbase);
        const int i_hi  = min(tid, rbase + nrows - 1);
        #pragma unroll 4
        for (int i = i_lo; i <= i_hi; ++i) {
            float v = cur[(i - rbase) * EE + (tid - i)];  // lanes consecutive: no conflicts
            s1 += v;
            s2 = fmaf(v, v, s2);
        }

        __syncthreads();   // everyone done with this buffer
        if (kk + 2 < nk && tid == 0) {
            uint32_t bytes = (uint32_t)tile_rows(kk + 2) * EE * 4;
            mbar_expect_tx(m, bytes);
            bulk_ld(sbuf + (kk & 1) * TILE_BYTES,
                    xb + (size_t)(k0 + kk + 2) * TILE_FLOATS, bytes, m);
        }
    }

    // Single atomic pair per thread per chunk.
    const int t    = K + tid;
    const int tmax = min(K + nk * RR, TT) - 1 + (EE - 1);
    if (tid < NDIAG && t <= tmax) {
        atomicAdd(&g_S1[b * LL + t], s1);
        atomicAdd(&g_S2[b * LL + t], s2);
    }
}

// ---------------------------------------------------------------------------
// Kernel 2: READ-ONLY finalize. var = S2/c - (S1/c)^2, mean, * 0.1.
// One float4 per thread from each array (max MLP, no loop); plain
// atomicAdd into out[0] (zeroed by diag earlier in the stream).
// ---------------------------------------------------------------------------
__global__ void __launch_bounds__(256) tcl_finalize_kernel(float* __restrict__ out) {
    __shared__ float red[8];
    const int i = blockIdx.x * blockDim.x + threadIdx.x;   // < BB*LL/4
    float4 s1v = ((const float4*)g_S1)[i];
    float4 s2v = ((const float4*)g_S2)[i];

    float local = 0.0f;
    const int g0 = i * 4;
    #pragma unroll
    for (int j = 0; j < 4; ++j) {
        int t  = (g0 + j) & (LL - 1);              // LL is a power of two
        int ci = min(min(t + 1, EE), LL - t);
        float inv_c = 1.0f / (float)ci;
        float s1 = (j == 0) ? s1v.x : (j == 1) ? s1v.y : (j == 2) ? s1v.z : s1v.w;
        float s2 = (j == 0) ? s2v.x : (j == 1) ? s2v.y : (j == 2) ? s2v.z : s2v.w;
        float mean = s1 * inv_c;
        local += s2 * inv_c - mean * mean;
    }

    #pragma unroll
    for (int o = 16; o; o >>= 1) local += __shfl_down_sync(0xFFFFFFFFu, local, o);
    if ((threadIdx.x & 31) == 0) red[threadIdx.x >> 5] = local;
    __syncthreads();
    if (threadIdx.x < 8) {
        float v = red[threadIdx.x];
        #pragma unroll
        for (int o = 4; o; o >>= 1) v += __shfl_down_sync(0xFFu, v, o);
        if (threadIdx.x == 0) {
            atomicAdd(out, v * (0.1f / ((float)BB * (float)LL)));
        }
    }
}

// ---------------------------------------------------------------------------
// Kernel 3: zero scratch for the NEXT replay (runs after finalize).
// ---------------------------------------------------------------------------
__global__ void __launch_bounds__(256) tcl_postinit_kernel() {
    const int i = blockIdx.x * blockDim.x + threadIdx.x;   // < BB*LL/4
    float4 z = make_float4(0.f, 0.f, 0.f, 0.f);
    ((float4*)g_S1)[i] = z;
    ((float4*)g_S2)[i] = z;
}

// ---------------------------------------------------------------------------
extern "C" void kernel_launch(void* const* d_in, const int* in_sizes, int n_in,
                              void* d_out, int out_size) {
    const float* x = (const float*)d_in[0];
    float* out = (float*)d_out;

    const int diag_smem = 2 * TILE_BYTES;                  // 32 KB
    cudaFuncSetAttribute(tcl_diag_kernel,
                         cudaFuncAttributeMaxDynamicSharedMemorySize, diag_smem);
    dim3 grid(CHUNKS, BB);                                 // 256 x 16 = 4096
    tcl_diag_kernel<<<grid, 256, diag_smem>>>(x, out);

    tcl_finalize_kernel<<<BB * LL / 4 / 256, 256>>>(out);  // 512 blocks

    tcl_postinit_kernel<<<BB * LL / 4 / 256, 256>>>();     // 512 blocks
}